// round 11
// baseline (speedup 1.0000x reference)
#include <cuda_runtime.h>

#define NN    128
#define BATCH 2
#define LL    2048
#define CH    32          // chunk length S
#define NG    (LL/CH)     // 64 chunks per batch
#define NT    512         // threads for split-K kernels
#define PIT   129         // smem pitch (conflict-free)

// ---- device scratch (no allocation allowed) ----
__device__ float g_Ad[NN*NN];
__device__ float g_Bd[NN];
__device__ float g_pow[2][NN*NN];      // for Ad^S via squaring
__device__ float g_h[BATCH*NG*NN];     // local chunk contributions
__device__ float g_bound[BATCH*NG*NN]; // state entering each chunk

// ============================================================
// Kernel 1: SETUP (disc + 5x squaring in one cluster launch).
// 8 CTAs x 1024 threads.
//  - rank 0: D&C triangular inverse of P1 = I - 0.5A (lower tri)
//  - all ranks: 5 squaring rounds (16 rows/block, 512 active thr),
//    cluster barriers between; L2-coherent via threadfence + __ldcg.
// ============================================================
__global__ __launch_bounds__(1024, 1) __cluster_dims__(8, 1, 1)
void k_setup(const float* __restrict__ A, const float* __restrict__ B) {
    extern __shared__ float sm[];
    int tid = threadIdx.x;
    unsigned rank;
    asm("mov.u32 %0, %%cluster_ctarank;" : "=r"(rank));

    if (rank == 0) {
        float* sP = sm;                 // NN*PIT
        float* sM = sm + NN*PIT;        // NN*PIT
        float* sT = sm + 2*NN*PIT;      // 4096 temp

        for (int idx = tid; idx < NN*NN; idx += 1024) {
            int i = idx >> 7, j = idx & (NN-1);
            float iv = (i == j) ? 1.0f : 0.0f;
            sP[i*PIT + j] = iv - 0.5f * A[idx];
            sM[i*PIT + j] = 0.0f;
        }
        __syncthreads();

        // base: 16 diagonal 8x8 blocks, forward substitution
        if (tid < 128) {
            int blk = tid >> 3, col = tid & 7;
            int b0 = blk * 8;
            float x[8];
            #pragma unroll
            for (int i = 0; i < 8; i++) x[i] = 0.0f;
            for (int i = col; i < 8; i++) {
                float v = (i == col) ? 1.0f : 0.0f;
                for (int k = col; k < i; k++)
                    v -= sP[(b0+i)*PIT + b0 + k] * x[k];
                x[i] = v / sP[(b0+i)*PIT + b0 + i];
            }
            #pragma unroll
            for (int i = 0; i < 8; i++)
                sM[(b0+i)*PIT + b0 + col] = x[i];
        }
        __syncthreads();

        // 4 combine levels
        for (int s = 8; s <= 64; s <<= 1) {
            int npairs = NN / (2*s);
            int total  = npairs * s * s;
            for (int idx = tid; idx < total; idx += 1024) {
                int p = idx / (s*s);
                int rem = idx - p*s*s;
                int i = rem / s, j = rem - i*s;
                int r0 = 2*p*s;
                float acc = 0.0f;
                #pragma unroll 4
                for (int k = 0; k < s; k++)
                    acc = fmaf(sM[(r0+s+i)*PIT + r0+s+k],
                               sP[(r0+s+k)*PIT + r0+j], acc);
                sT[idx] = acc;
            }
            __syncthreads();
            for (int idx = tid; idx < total; idx += 1024) {
                int p = idx / (s*s);
                int rem = idx - p*s*s;
                int i = rem / s, j = rem - i*s;
                int r0 = 2*p*s;
                float acc = 0.0f;
                const float* tp = sT + p*s*s + i*s;
                #pragma unroll 4
                for (int k = 0; k < s; k++)
                    acc = fmaf(tp[k], sM[(r0+k)*PIT + r0+j], acc);
                sM[(r0+s+i)*PIT + r0+j] = -acc;
            }
            __syncthreads();
        }

        for (int idx = tid; idx < NN*NN; idx += 1024) {
            int i = idx >> 7, j = idx & (NN-1);
            float m = sM[i*PIT + j];
            float ad = 2.0f * m - ((i == j) ? 1.0f : 0.0f);
            g_Ad[idx] = ad;
            g_pow[0][idx] = ad;
        }
        if (tid < NN) {
            float acc = 0.0f;
            for (int j = 0; j <= tid; j++)
                acc = fmaf(sM[tid*PIT + j], B[j], acc);
            g_Bd[tid] = acc;
        }
    }
    __threadfence();
    __syncthreads();
    asm volatile("barrier.cluster.arrive.aligned;" ::: "memory");
    asm volatile("barrier.cluster.wait.aligned;"   ::: "memory");

    // ---- 5 squarings: src/dst alternate, end in g_pow[1] ----
    float*  sB  = sm;                   // reuse first 64KB
    float4* sB4 = (float4*)sB;
    for (int it = 0; it < 5; it++) {
        const float4* s4 = (const float4*)g_pow[it & 1];
        float* dst = g_pow[(it & 1) ^ 1];
        // stage full src (64KB) via L1-bypassing loads
        #pragma unroll
        for (int u = 0; u < 4; u++)
            sB4[tid + 1024*u] = __ldcg(s4 + tid + 1024*u);
        __syncthreads();
        // 512 active threads: one row per (tid>>5), 16 rows/block
        if (tid < 512) {
            int row = rank*16 + (tid >> 5);
            int c4  = tid & 31;
            const float* ra = sB + row*NN;
            float4 acc = make_float4(0.f,0.f,0.f,0.f);
            #pragma unroll 8
            for (int k = 0; k < NN; k++) {
                float4 bv = sB4[k*32 + c4];
                float a0 = ra[k];
                acc.x = fmaf(a0, bv.x, acc.x);
                acc.y = fmaf(a0, bv.y, acc.y);
                acc.z = fmaf(a0, bv.z, acc.z);
                acc.w = fmaf(a0, bv.w, acc.w);
            }
            ((float4*)(dst + row*NN))[c4] = acc;
        }
        __threadfence();
        __syncthreads();
        asm volatile("barrier.cluster.arrive.aligned;" ::: "memory");
        asm volatile("barrier.cluster.wait.aligned;"   ::: "memory");
    }
}

// ============================================================
// Kernel 2: phase A, 512 threads, 4-way split-K.
// Thread (r = tid&127, q = tid>>7) owns Ad[r, 32q:32q+32] in regs.
// ============================================================
__global__ __launch_bounds__(NT, 1) void k_phaseA(const float* __restrict__ f) {
    extern __shared__ float sm[];
    float* sAd = sm;               // NN*PIT
    float* sc  = sAd + NN*PIT;     // NN
    float* sf  = sc + NN;          // CH
    float* sp  = sf + CH;          // NT partials
    int tid = threadIdx.x;
    int r = tid & (NN-1), q = tid >> 7;
    int g = blockIdx.x, b = blockIdx.y;

    for (int idx = tid; idx < NN*NN; idx += NT) {
        int i = idx >> 7, j = idx & (NN-1);
        sAd[i*PIT + j] = g_Ad[idx];
    }
    if (tid < CH) sf[tid] = f[b*LL + g*CH + tid];
    if (tid < NN) sc[tid] = 0.0f;
    __syncthreads();

    float a[32];
    #pragma unroll
    for (int u = 0; u < 32; u++) a[u] = sAd[r*PIT + 32*q + u];
    float bd = (q == 0) ? g_Bd[r] : 0.0f;

    float cn = 0.0f;
    for (int t = 0; t < CH; t++) {
        float acc0 = (q == 0) ? bd * sf[t] : 0.f;
        float acc1 = 0.f, acc2 = 0.f, acc3 = 0.f;
        const float4* sc4 = (const float4*)sc;
        #pragma unroll
        for (int u4 = 0; u4 < 8; u4++) {
            float4 v = sc4[8*q + u4];
            acc0 = fmaf(a[4*u4+0], v.x, acc0);
            acc1 = fmaf(a[4*u4+1], v.y, acc1);
            acc2 = fmaf(a[4*u4+2], v.z, acc2);
            acc3 = fmaf(a[4*u4+3], v.w, acc3);
        }
        sp[q*NN + r] = (acc0 + acc1) + (acc2 + acc3);
        __syncthreads();
        if (q == 0) {
            cn = (sp[r] + sp[NN+r]) + (sp[2*NN+r] + sp[3*NN+r]);
            sc[r] = cn;
        }
        __syncthreads();
    }
    if (q == 0) g_h[(b*NG + g)*NN + r] = cn;
}

// ============================================================
// Kernel 3: boundary prefix, 512 threads, 4-way split-K.
// C_{g+1} = Ad^S * C_g + h_g.  One block per batch.
// ============================================================
__global__ __launch_bounds__(NT, 1) void k_phaseB() {
    extern __shared__ float sm[];
    float* sA = sm;             // NN*PIT
    float* sc = sA + NN*PIT;    // NN
    float* sp = sc + NN;        // NT
    int tid = threadIdx.x;
    int r = tid & (NN-1), q = tid >> 7;
    int b = blockIdx.x;
    const float* AdS = g_pow[1];   // Ad^32 after 5 squarings
    for (int idx = tid; idx < NN*NN; idx += NT) {
        int i = idx >> 7, j = idx & (NN-1);
        sA[i*PIT + j] = AdS[idx];
    }
    if (tid < NN) sc[tid] = 0.0f;
    __syncthreads();
    float a[32];
    #pragma unroll
    for (int u = 0; u < 32; u++) a[u] = sA[r*PIT + 32*q + u];

    float cn = 0.0f;
    for (int g = 0; g < NG; g++) {
        if (q == 0) g_bound[(b*NG + g)*NN + r] = cn;
        float acc0 = (q == 0) ? __ldg(g_h + (b*NG + g)*NN + r) : 0.f;
        float acc1 = 0.f, acc2 = 0.f, acc3 = 0.f;
        const float4* sc4 = (const float4*)sc;
        #pragma unroll
        for (int u4 = 0; u4 < 8; u4++) {
            float4 v = sc4[8*q + u4];
            acc0 = fmaf(a[4*u4+0], v.x, acc0);
            acc1 = fmaf(a[4*u4+1], v.y, acc1);
            acc2 = fmaf(a[4*u4+2], v.z, acc2);
            acc3 = fmaf(a[4*u4+3], v.w, acc3);
        }
        sp[q*NN + r] = (acc0 + acc1) + (acc2 + acc3);
        __syncthreads();
        if (q == 0) {
            cn = (sp[r] + sp[NN+r]) + (sp[2*NN+r] + sp[3*NN+r]);
            sc[r] = cn;
        }
        __syncthreads();
    }
}

// ============================================================
// Kernel 4: FUSED phase C + expand, INTERLEAVED.
// Each step: split-K matvec -> state barrier -> all 512 threads
// immediately stream the 64KB tile for this step (1 LDS.128 +
// 8 STG.128 each). Store issue hides the matvec compute.
// ============================================================
__global__ __launch_bounds__(NT, 1) void k_fusedC(const float* __restrict__ f,
                                                  const float* __restrict__ Cv,
                                                  const float* __restrict__ Dv,
                                                  float* __restrict__ ys,
                                                  float* __restrict__ cfin) {
    extern __shared__ float sm[];
    float* sAd = sm;               // NN*PIT
    float* sc  = sAd + NN*PIT;     // NN current state
    float* sf  = sc + NN;          // CH
    float* sC  = sf + CH;          // NN
    float* sp  = sC + NN;          // NT
    int tid = threadIdx.x;
    int r = tid & (NN-1), q = tid >> 7;
    int g = blockIdx.x, b = blockIdx.y;

    for (int idx = tid; idx < NN*NN; idx += NT) {
        int i = idx >> 7, j = idx & (NN-1);
        sAd[i*PIT + j] = g_Ad[idx];
    }
    if (tid < CH) sf[tid] = f[b*LL + g*CH + tid];
    if (tid < NN) {
        sC[tid] = Cv[tid];
        sc[tid] = g_bound[(b*NG + g)*NN + tid];
    }
    __syncthreads();

    float a[32];
    #pragma unroll
    for (int u = 0; u < 32; u++) a[u] = sAd[r*PIT + 32*q + u];
    float bd  = (q == 0) ? g_Bd[r] : 0.0f;
    float dv0 = Dv[0];

    // hoisted C values for the store stream (constant across t)
    float cn_[8];
    int nb = tid >> 5;
    #pragma unroll
    for (int it = 0; it < 8; it++) cn_[it] = sC[nb + 16*it];
    int lane = tid & 31;
    float4* outbase = (float4*)(ys + (size_t)(b*LL + g*CH) * NN * NN);

    for (int t = 0; t < CH; t++) {
        float ft = sf[t];
        float acc0 = (q == 0) ? bd * ft : 0.f;
        float acc1 = 0.f, acc2 = 0.f, acc3 = 0.f;
        const float4* sc4 = (const float4*)sc;
        #pragma unroll
        for (int u4 = 0; u4 < 8; u4++) {
            float4 v = sc4[8*q + u4];
            acc0 = fmaf(a[4*u4+0], v.x, acc0);
            acc1 = fmaf(a[4*u4+1], v.y, acc1);
            acc2 = fmaf(a[4*u4+2], v.z, acc2);
            acc3 = fmaf(a[4*u4+3], v.w, acc3);
        }
        sp[q*NN + r] = (acc0 + acc1) + (acc2 + acc3);
        __syncthreads();
        if (q == 0)
            sc[r] = (sp[r] + sp[NN+r]) + (sp[2*NN+r] + sp[3*NN+r]);
        __syncthreads();
        // stream this step's 64KB tile (stores overlap next step's compute)
        float4 cv = ((const float4*)sc)[lane];
        float  df = dv0 * ft;
        float4* out = outbase + (size_t)t * (NN*NN/4);
        #pragma unroll
        for (int it = 0; it < 8; it++) {
            int idx = tid + NT*it;
            float4 v;
            v.x = fmaf(cn_[it], cv.x, df);
            v.y = fmaf(cn_[it], cv.y, df);
            v.z = fmaf(cn_[it], cv.z, df);
            v.w = fmaf(cn_[it], cv.w, df);
            __stcs(&out[idx], v);
        }
    }
    if (cfin != nullptr && g == NG-1 && tid < NN)
        cfin[b*NN + tid] = sc[tid];
}

// ============================================================
extern "C" void kernel_launch(void* const* d_in, const int* in_sizes, int n_in,
                              void* d_out, int out_size) {
    const float* f = (const float*)d_in[0];
    const float* A = (const float*)d_in[1];
    const float* B = (const float*)d_in[2];
    const float* C = (const float*)d_in[3];
    const float* D = (const float*)d_in[4];
    float* out = (float*)d_out;

    const long long ysz = (long long)BATCH * LL * NN * NN;   // 67108864
    const int cf = BATCH * NN;                               // 256
    float* cfin = nullptr;
    float* ys   = out;
    if ((long long)out_size == ysz + cf) { cfin = out; ys = out + cf; }

    const int smem_setup = (2*NN*PIT + 4096)*4;              // 148480
    const int smem_pA    = (NN*PIT + NN + CH + NT)*4;        // 68736
    const int smem_pB    = (NN*PIT + NN + NT)*4;             // 68608
    const int smem_fC    = (NN*PIT + NN + CH + NN + NT)*4;   // 69248
    cudaFuncSetAttribute(k_setup,  cudaFuncAttributeMaxDynamicSharedMemorySize, smem_setup);
    cudaFuncSetAttribute(k_phaseA, cudaFuncAttributeMaxDynamicSharedMemorySize, smem_pA);
    cudaFuncSetAttribute(k_phaseB, cudaFuncAttributeMaxDynamicSharedMemorySize, smem_pB);
    cudaFuncSetAttribute(k_fusedC, cudaFuncAttributeMaxDynamicSharedMemorySize, smem_fC);

    // 1) setup: discretize + Ad^32 (cluster kernel, one launch)
    k_setup<<<8, 1024, smem_setup>>>(A, B);
    // 2) phase A — local chunk contributions
    dim3 gA(NG, BATCH);
    k_phaseA<<<gA, NT, smem_pA>>>(f);
    // 3) boundary prefix
    k_phaseB<<<BATCH, NT, smem_pB>>>();
    // 4) fused phase C + expand: interleaved 268MB streaming store
    k_fusedC<<<gA, NT, smem_fC>>>(f, C, D, ys, cfin);
}

// round 12
// speedup vs baseline: 1.2191x; 1.2191x over previous
#include <cuda_runtime.h>

#define NN    128
#define BATCH 2
#define LL    2048
#define CH    32          // chunk length S
#define NG    (LL/CH)     // 64 chunks per batch
#define NT    512         // threads for split-K kernels
#define PIT   129         // smem pitch (conflict-free)

// ---- device scratch (no allocation allowed) ----
__device__ float g_Ad[NN*NN];
__device__ float g_Bd[NN];
__device__ float g_pow[2][NN*NN];      // for Ad^S via squaring
__device__ float g_h[BATCH*NG*NN];     // local chunk contributions
__device__ float g_bound[BATCH*NG*NN]; // state entering each chunk

// ============================================================
// Kernel 1: discretize via WARP-PER-COLUMN forward substitution.
// P1 = I - 0.5A (lower triangular). Column j of Minv solves
// P1 x = e_j  (independent per column -> 128 parallel warps).
// Ad = 2*Minv - I.  4 blocks x 1024 threads (32 columns/block).
// ============================================================
__global__ __launch_bounds__(1024, 1) void k_disc(const float* __restrict__ A) {
    extern __shared__ float sm[];
    float* sL = sm;                  // NN*PIT
    float* sx = sm + NN*PIT;         // 32 columns * 132
    int tid  = threadIdx.x;
    int w    = tid >> 5, lane = tid & 31;
    int j    = blockIdx.x * 32 + w;  // this warp's column

    for (int idx = tid; idx < NN*NN; idx += 1024) {
        int i = idx >> 7, jj = idx & (NN-1);
        sL[i*PIT + jj] = ((i == jj) ? 1.0f : 0.0f) - 0.5f * A[idx];
    }
    __syncthreads();

    float* x = sx + w*132;
    // forward substitution: x[i] = (e_ij - sum_{k<i} L[i,k] x[k]) / L[i,i]
    for (int i = j; i < NN; i++) {
        float p = 0.0f;
        for (int k = j + lane; k < i; k += 32)
            p = fmaf(sL[i*PIT + k], x[k], p);
        p += __shfl_xor_sync(0xffffffffu, p, 16);
        p += __shfl_xor_sync(0xffffffffu, p, 8);
        p += __shfl_xor_sync(0xffffffffu, p, 4);
        p += __shfl_xor_sync(0xffffffffu, p, 2);
        p += __shfl_xor_sync(0xffffffffu, p, 1);
        if (lane == 0)
            x[i] = (((i == j) ? 1.0f : 0.0f) - p) / sL[i*PIT + i];
        __syncwarp();
    }
    // write Ad column j (Ad = 2*Minv - I; Minv upper part is 0)
    for (int i = lane; i < NN; i += 32) {
        float m  = (i >= j) ? x[i] : 0.0f;
        float ad = 2.0f * m - ((i == j) ? 1.0f : 0.0f);
        g_Ad[i*NN + j]    = ad;
        g_pow[0][i*NN + j] = ad;
    }
}

// ============================================================
// Kernel 2: Bd + Ad^32. Cluster of 8 CTAs x 1024 threads.
// rank 0 prologue: Bd = 0.5*(Ad@B + B)   (Minv = (Ad+I)/2)
// all ranks: 5 squaring rounds, 16 rows/block, cluster barriers;
// L2-coherent via threadfence + __ldcg staging.
// ============================================================
__global__ __launch_bounds__(1024, 1) __cluster_dims__(8, 1, 1)
void k_sq5(const float* __restrict__ B) {
    extern __shared__ float sm[];
    int tid = threadIdx.x;
    unsigned rank;
    asm("mov.u32 %0, %%cluster_ctarank;" : "=r"(rank));

    if (rank == 0 && tid < NN) {
        float acc = 0.0f;
        const float* row = g_Ad + tid*NN;
        #pragma unroll 8
        for (int jj = 0; jj < NN; jj++)
            acc = fmaf(__ldg(row + jj), __ldg(B + jj), acc);
        g_Bd[tid] = 0.5f * (acc + B[tid]);
    }

    float*  sB  = sm;                   // 64KB staging
    float4* sB4 = (float4*)sB;
    for (int it = 0; it < 5; it++) {
        const float4* s4 = (const float4*)g_pow[it & 1];
        float* dst = g_pow[(it & 1) ^ 1];
        #pragma unroll
        for (int u = 0; u < 4; u++)
            sB4[tid + 1024*u] = __ldcg(s4 + tid + 1024*u);
        __syncthreads();
        if (tid < 512) {
            int row = rank*16 + (tid >> 5);
            int c4  = tid & 31;
            const float* ra = sB + row*NN;
            float4 acc = make_float4(0.f,0.f,0.f,0.f);
            #pragma unroll 8
            for (int k = 0; k < NN; k++) {
                float4 bv = sB4[k*32 + c4];
                float a0 = ra[k];
                acc.x = fmaf(a0, bv.x, acc.x);
                acc.y = fmaf(a0, bv.y, acc.y);
                acc.z = fmaf(a0, bv.z, acc.z);
                acc.w = fmaf(a0, bv.w, acc.w);
            }
            ((float4*)(dst + row*NN))[c4] = acc;
        }
        __threadfence();
        __syncthreads();
        asm volatile("barrier.cluster.arrive.aligned;" ::: "memory");
        asm volatile("barrier.cluster.wait.aligned;"   ::: "memory");
    }
}

// ============================================================
// Kernel 3: phase A, 512 threads, 4-way split-K.
// ============================================================
__global__ __launch_bounds__(NT, 1) void k_phaseA(const float* __restrict__ f) {
    extern __shared__ float sm[];
    float* sAd = sm;               // NN*PIT
    float* sc  = sAd + NN*PIT;     // NN
    float* sf  = sc + NN;          // CH
    float* sp  = sf + CH;          // NT partials
    int tid = threadIdx.x;
    int r = tid & (NN-1), q = tid >> 7;
    int g = blockIdx.x, b = blockIdx.y;

    for (int idx = tid; idx < NN*NN; idx += NT) {
        int i = idx >> 7, j = idx & (NN-1);
        sAd[i*PIT + j] = g_Ad[idx];
    }
    if (tid < CH) sf[tid] = f[b*LL + g*CH + tid];
    if (tid < NN) sc[tid] = 0.0f;
    __syncthreads();

    float a[32];
    #pragma unroll
    for (int u = 0; u < 32; u++) a[u] = sAd[r*PIT + 32*q + u];
    float bd = (q == 0) ? g_Bd[r] : 0.0f;

    float cn = 0.0f;
    for (int t = 0; t < CH; t++) {
        float acc0 = (q == 0) ? bd * sf[t] : 0.f;
        float acc1 = 0.f, acc2 = 0.f, acc3 = 0.f;
        const float4* sc4 = (const float4*)sc;
        #pragma unroll
        for (int u4 = 0; u4 < 8; u4++) {
            float4 v = sc4[8*q + u4];
            acc0 = fmaf(a[4*u4+0], v.x, acc0);
            acc1 = fmaf(a[4*u4+1], v.y, acc1);
            acc2 = fmaf(a[4*u4+2], v.z, acc2);
            acc3 = fmaf(a[4*u4+3], v.w, acc3);
        }
        sp[q*NN + r] = (acc0 + acc1) + (acc2 + acc3);
        __syncthreads();
        if (q == 0) {
            cn = (sp[r] + sp[NN+r]) + (sp[2*NN+r] + sp[3*NN+r]);
            sc[r] = cn;
        }
        __syncthreads();
    }
    if (q == 0) g_h[(b*NG + g)*NN + r] = cn;
}

// ============================================================
// Kernel 4: boundary prefix, 512 threads, 4-way split-K.
// ============================================================
__global__ __launch_bounds__(NT, 1) void k_phaseB() {
    extern __shared__ float sm[];
    float* sA = sm;             // NN*PIT
    float* sc = sA + NN*PIT;    // NN
    float* sp = sc + NN;        // NT
    int tid = threadIdx.x;
    int r = tid & (NN-1), q = tid >> 7;
    int b = blockIdx.x;
    const float* AdS = g_pow[1];   // Ad^32 after 5 squarings
    for (int idx = tid; idx < NN*NN; idx += NT) {
        int i = idx >> 7, j = idx & (NN-1);
        sA[i*PIT + j] = AdS[idx];
    }
    if (tid < NN) sc[tid] = 0.0f;
    __syncthreads();
    float a[32];
    #pragma unroll
    for (int u = 0; u < 32; u++) a[u] = sA[r*PIT + 32*q + u];

    float cn = 0.0f;
    for (int g = 0; g < NG; g++) {
        if (q == 0) g_bound[(b*NG + g)*NN + r] = cn;
        float acc0 = (q == 0) ? __ldg(g_h + (b*NG + g)*NN + r) : 0.f;
        float acc1 = 0.f, acc2 = 0.f, acc3 = 0.f;
        const float4* sc4 = (const float4*)sc;
        #pragma unroll
        for (int u4 = 0; u4 < 8; u4++) {
            float4 v = sc4[8*q + u4];
            acc0 = fmaf(a[4*u4+0], v.x, acc0);
            acc1 = fmaf(a[4*u4+1], v.y, acc1);
            acc2 = fmaf(a[4*u4+2], v.z, acc2);
            acc3 = fmaf(a[4*u4+3], v.w, acc3);
        }
        sp[q*NN + r] = (acc0 + acc1) + (acc2 + acc3);
        __syncthreads();
        if (q == 0) {
            cn = (sp[r] + sp[NN+r]) + (sp[2*NN+r] + sp[3*NN+r]);
            sc[r] = cn;
        }
        __syncthreads();
    }
}

// ============================================================
// Kernel 5: FUSED phase C + expand, TWO-PASS (round-10, measured 53.5us).
// Pass 1: 32-step recurrence into smem state buffer.
// Pass 2: barrier-free streaming store (1 LDS.128 + 8 STG.128 per t).
// ============================================================
__global__ __launch_bounds__(NT, 1) void k_fusedC(const float* __restrict__ f,
                                                  const float* __restrict__ Cv,
                                                  const float* __restrict__ Dv,
                                                  float* __restrict__ ys,
                                                  float* __restrict__ cfin) {
    extern __shared__ float sm[];
    float* sAd = sm;               // NN*PIT
    float* sSt = sAd + NN*PIT;     // CH*NN states
    float* sc  = sSt + CH*NN;      // NN current state
    float* sf  = sc + NN;          // CH
    float* sC  = sf + CH;          // NN
    float* sp  = sC + NN;          // NT
    int tid = threadIdx.x;
    int r = tid & (NN-1), q = tid >> 7;
    int g = blockIdx.x, b = blockIdx.y;

    for (int idx = tid; idx < NN*NN; idx += NT) {
        int i = idx >> 7, j = idx & (NN-1);
        sAd[i*PIT + j] = g_Ad[idx];
    }
    if (tid < CH) sf[tid] = f[b*LL + g*CH + tid];
    if (tid < NN) {
        sC[tid] = Cv[tid];
        sc[tid] = g_bound[(b*NG + g)*NN + tid];
    }
    __syncthreads();

    float a[32];
    #pragma unroll
    for (int u = 0; u < 32; u++) a[u] = sAd[r*PIT + 32*q + u];
    float bd  = (q == 0) ? g_Bd[r] : 0.0f;
    float dv0 = Dv[0];

    // ---- pass 1: recurrence into sSt ----
    for (int t = 0; t < CH; t++) {
        float acc0 = (q == 0) ? bd * sf[t] : 0.f;
        float acc1 = 0.f, acc2 = 0.f, acc3 = 0.f;
        const float4* sc4 = (const float4*)sc;
        #pragma unroll
        for (int u4 = 0; u4 < 8; u4++) {
            float4 v = sc4[8*q + u4];
            acc0 = fmaf(a[4*u4+0], v.x, acc0);
            acc1 = fmaf(a[4*u4+1], v.y, acc1);
            acc2 = fmaf(a[4*u4+2], v.z, acc2);
            acc3 = fmaf(a[4*u4+3], v.w, acc3);
        }
        sp[q*NN + r] = (acc0 + acc1) + (acc2 + acc3);
        __syncthreads();
        if (q == 0) {
            float cn = (sp[r] + sp[NN+r]) + (sp[2*NN+r] + sp[3*NN+r]);
            sc[r] = cn;
            sSt[t*NN + r] = cn;
        }
        __syncthreads();
    }

    // ---- pass 2: barrier-free streaming store ----
    float cn_[8];
    int nb = tid >> 5;
    #pragma unroll
    for (int it = 0; it < 8; it++) cn_[it] = sC[nb + 16*it];
    int lane = tid & 31;
    float4* outbase = (float4*)(ys + (size_t)(b*LL + g*CH) * NN * NN);
    const float4* st4 = (const float4*)sSt;

    for (int t = 0; t < CH; t++) {
        float4 cv = st4[t*(NN/4) + lane];
        float  df = dv0 * sf[t];
        float4* out = outbase + (size_t)t * (NN*NN/4);
        #pragma unroll
        for (int it = 0; it < 8; it++) {
            int idx = tid + NT*it;
            float4 v;
            v.x = fmaf(cn_[it], cv.x, df);
            v.y = fmaf(cn_[it], cv.y, df);
            v.z = fmaf(cn_[it], cv.z, df);
            v.w = fmaf(cn_[it], cv.w, df);
            __stcs(&out[idx], v);
        }
    }
    if (cfin != nullptr && g == NG-1 && tid < NN)
        cfin[b*NN + tid] = sSt[(CH-1)*NN + tid];
}

// ============================================================
extern "C" void kernel_launch(void* const* d_in, const int* in_sizes, int n_in,
                              void* d_out, int out_size) {
    const float* f = (const float*)d_in[0];
    const float* A = (const float*)d_in[1];
    const float* B = (const float*)d_in[2];
    const float* C = (const float*)d_in[3];
    const float* D = (const float*)d_in[4];
    float* out = (float*)d_out;

    const long long ysz = (long long)BATCH * LL * NN * NN;   // 67108864
    const int cf = BATCH * NN;                               // 256
    float* cfin = nullptr;
    float* ys   = out;
    if ((long long)out_size == ysz + cf) { cfin = out; ys = out + cf; }

    const int smem_disc = (NN*PIT + 32*132)*4;               // 82944
    const int smem_sq5  = NN*NN*4;                           // 65536
    const int smem_pA   = (NN*PIT + NN + CH + NT)*4;         // 68736
    const int smem_pB   = (NN*PIT + NN + NT)*4;              // 68608
    const int smem_fC   = (NN*PIT + CH*NN + NN + CH + NN + NT)*4; // 85632
    cudaFuncSetAttribute(k_disc,   cudaFuncAttributeMaxDynamicSharedMemorySize, smem_disc);
    cudaFuncSetAttribute(k_sq5,    cudaFuncAttributeMaxDynamicSharedMemorySize, smem_sq5);
    cudaFuncSetAttribute(k_phaseA, cudaFuncAttributeMaxDynamicSharedMemorySize, smem_pA);
    cudaFuncSetAttribute(k_phaseB, cudaFuncAttributeMaxDynamicSharedMemorySize, smem_pB);
    cudaFuncSetAttribute(k_fusedC, cudaFuncAttributeMaxDynamicSharedMemorySize, smem_fC);

    // 1) discretize: warp-per-column triangular solves (parallel)
    k_disc<<<4, 1024, smem_disc>>>(A);
    // 2) Bd + Ad^32 via 5 in-kernel squarings (cluster)
    k_sq5<<<8, 1024, smem_sq5>>>(B);
    // 3) phase A — local chunk contributions
    dim3 gA(NG, BATCH);
    k_phaseA<<<gA, NT, smem_pA>>>(f);
    // 4) boundary prefix
    k_phaseB<<<BATCH, NT, smem_pB>>>();
    // 5) fused phase C + expand (two-pass streaming store)
    k_fusedC<<<gA, NT, smem_fC>>>(f, C, D, ys, cfin);
}

// round 13
// speedup vs baseline: 1.5268x; 1.2524x over previous
#include <cuda_runtime.h>

#define NN    128
#define BATCH 2
#define LL    2048
#define CH    32          // chunk length S
#define NG    (LL/CH)     // 64 chunks per batch
#define NT    512         // threads for split-K kernels
#define PIT   129         // smem pitch (conflict-free)

// ---- device scratch (no allocation allowed) ----
__device__ float g_Ad[NN*NN];
__device__ float g_Bd[NN];
__device__ float g_pow[2][NN*NN];      // for Ad^S via squaring
__device__ float g_h[BATCH*NG*NN];     // local chunk contributions
__device__ float g_bound[BATCH*NG*NN]; // state entering each chunk

// ============================================================
// Kernel 1: discretize via D&C triangular inverse (round-8 design).
// P1 = I - 0.5A is LOWER TRIANGULAR. One block, 1024 threads.
//   base: 16 parallel 8x8 diagonal-block inverses
//   4 combine levels: Minv21 = -Minv22 * L21 * Minv11
// Writes Ad = 2*Minv - I to g_Ad and g_pow[0]. (Bd done in k_sq5.)
// ============================================================
__global__ __launch_bounds__(1024, 1) void k_disc(const float* __restrict__ A) {
    extern __shared__ float sm[];
    float* sP = sm;                 // NN*PIT
    float* sM = sm + NN*PIT;        // NN*PIT
    float* sT = sm + 2*NN*PIT;      // 4096 temp
    int tid = threadIdx.x;

    for (int idx = tid; idx < NN*NN; idx += 1024) {
        int i = idx >> 7, j = idx & (NN-1);
        float iv = (i == j) ? 1.0f : 0.0f;
        sP[i*PIT + j] = iv - 0.5f * A[idx];
        sM[i*PIT + j] = 0.0f;
    }
    __syncthreads();

    // base: 16 diagonal 8x8 blocks, forward substitution
    if (tid < 128) {
        int blk = tid >> 3, col = tid & 7;
        int b0 = blk * 8;
        float x[8];
        #pragma unroll
        for (int i = 0; i < 8; i++) x[i] = 0.0f;
        for (int i = col; i < 8; i++) {
            float v = (i == col) ? 1.0f : 0.0f;
            for (int k = col; k < i; k++)
                v -= sP[(b0+i)*PIT + b0 + k] * x[k];
            x[i] = v / sP[(b0+i)*PIT + b0 + i];
        }
        #pragma unroll
        for (int i = 0; i < 8; i++)
            sM[(b0+i)*PIT + b0 + col] = x[i];
    }
    __syncthreads();

    // 4 combine levels
    for (int s = 8; s <= 64; s <<= 1) {
        int npairs = NN / (2*s);
        int total  = npairs * s * s;
        for (int idx = tid; idx < total; idx += 1024) {
            int p = idx / (s*s);
            int rem = idx - p*s*s;
            int i = rem / s, j = rem - i*s;
            int r0 = 2*p*s;
            float acc = 0.0f;
            #pragma unroll 4
            for (int k = 0; k < s; k++)
                acc = fmaf(sM[(r0+s+i)*PIT + r0+s+k],
                           sP[(r0+s+k)*PIT + r0+j], acc);
            sT[idx] = acc;
        }
        __syncthreads();
        for (int idx = tid; idx < total; idx += 1024) {
            int p = idx / (s*s);
            int rem = idx - p*s*s;
            int i = rem / s, j = rem - i*s;
            int r0 = 2*p*s;
            float acc = 0.0f;
            const float* tp = sT + p*s*s + i*s;
            #pragma unroll 4
            for (int k = 0; k < s; k++)
                acc = fmaf(tp[k], sM[(r0+k)*PIT + r0+j], acc);
            sM[(r0+s+i)*PIT + r0+j] = -acc;
        }
        __syncthreads();
    }

    for (int idx = tid; idx < NN*NN; idx += 1024) {
        int i = idx >> 7, j = idx & (NN-1);
        float m = sM[i*PIT + j];
        float ad = 2.0f * m - ((i == j) ? 1.0f : 0.0f);
        g_Ad[idx] = ad;
        g_pow[0][idx] = ad;
    }
}

// ============================================================
// Kernel 2: Bd + Ad^32. Cluster of 8 CTAs x 1024 threads.
// rank 0 prologue: Bd = 0.5*(Ad@B + B)   (Minv = (Ad+I)/2)
// all ranks: 5 squaring rounds, 16 rows/block, cluster barriers.
// ============================================================
__global__ __launch_bounds__(1024, 1) __cluster_dims__(8, 1, 1)
void k_sq5(const float* __restrict__ B) {
    extern __shared__ float sm[];
    int tid = threadIdx.x;
    unsigned rank;
    asm("mov.u32 %0, %%cluster_ctarank;" : "=r"(rank));

    if (rank == 0 && tid < NN) {
        float acc = 0.0f;
        const float* row = g_Ad + tid*NN;
        #pragma unroll 8
        for (int jj = 0; jj < NN; jj++)
            acc = fmaf(__ldg(row + jj), __ldg(B + jj), acc);
        g_Bd[tid] = 0.5f * (acc + B[tid]);
    }

    float*  sB  = sm;                   // 64KB staging
    float4* sB4 = (float4*)sB;
    for (int it = 0; it < 5; it++) {
        const float4* s4 = (const float4*)g_pow[it & 1];
        float* dst = g_pow[(it & 1) ^ 1];
        #pragma unroll
        for (int u = 0; u < 4; u++)
            sB4[tid + 1024*u] = __ldcg(s4 + tid + 1024*u);
        __syncthreads();
        if (tid < 512) {
            int row = rank*16 + (tid >> 5);
            int c4  = tid & 31;
            const float* ra = sB + row*NN;
            float4 acc = make_float4(0.f,0.f,0.f,0.f);
            #pragma unroll 8
            for (int k = 0; k < NN; k++) {
                float4 bv = sB4[k*32 + c4];
                float a0 = ra[k];
                acc.x = fmaf(a0, bv.x, acc.x);
                acc.y = fmaf(a0, bv.y, acc.y);
                acc.z = fmaf(a0, bv.z, acc.z);
                acc.w = fmaf(a0, bv.w, acc.w);
            }
            ((float4*)(dst + row*NN))[c4] = acc;
        }
        __threadfence();
        __syncthreads();
        asm volatile("barrier.cluster.arrive.aligned;" ::: "memory");
        asm volatile("barrier.cluster.wait.aligned;"   ::: "memory");
    }
}

// ============================================================
// Kernel 3: phase A, 512 threads, 4-way split-K.
// ============================================================
__global__ __launch_bounds__(NT, 1) void k_phaseA(const float* __restrict__ f) {
    extern __shared__ float sm[];
    float* sAd = sm;               // NN*PIT
    float* sc  = sAd + NN*PIT;     // NN
    float* sf  = sc + NN;          // CH
    float* sp  = sf + CH;          // NT partials
    int tid = threadIdx.x;
    int r = tid & (NN-1), q = tid >> 7;
    int g = blockIdx.x, b = blockIdx.y;

    for (int idx = tid; idx < NN*NN; idx += NT) {
        int i = idx >> 7, j = idx & (NN-1);
        sAd[i*PIT + j] = g_Ad[idx];
    }
    if (tid < CH) sf[tid] = f[b*LL + g*CH + tid];
    if (tid < NN) sc[tid] = 0.0f;
    __syncthreads();

    float a[32];
    #pragma unroll
    for (int u = 0; u < 32; u++) a[u] = sAd[r*PIT + 32*q + u];
    float bd = (q == 0) ? g_Bd[r] : 0.0f;

    float cn = 0.0f;
    for (int t = 0; t < CH; t++) {
        float acc0 = (q == 0) ? bd * sf[t] : 0.f;
        float acc1 = 0.f, acc2 = 0.f, acc3 = 0.f;
        const float4* sc4 = (const float4*)sc;
        #pragma unroll
        for (int u4 = 0; u4 < 8; u4++) {
            float4 v = sc4[8*q + u4];
            acc0 = fmaf(a[4*u4+0], v.x, acc0);
            acc1 = fmaf(a[4*u4+1], v.y, acc1);
            acc2 = fmaf(a[4*u4+2], v.z, acc2);
            acc3 = fmaf(a[4*u4+3], v.w, acc3);
        }
        sp[q*NN + r] = (acc0 + acc1) + (acc2 + acc3);
        __syncthreads();
        if (q == 0) {
            cn = (sp[r] + sp[NN+r]) + (sp[2*NN+r] + sp[3*NN+r]);
            sc[r] = cn;
        }
        __syncthreads();
    }
    if (q == 0) g_h[(b*NG + g)*NN + r] = cn;
}

// ============================================================
// Kernel 4: boundary prefix with PRE-STAGED h (32KB in smem).
// The 64-step serial loop touches ONLY smem/FMA/barriers; the
// g_bound stores are fire-and-forget STG off the critical path.
// ============================================================
__global__ __launch_bounds__(NT, 1) void k_phaseB() {
    extern __shared__ float sm[];
    float* sA = sm;             // NN*PIT
    float* sh = sA + NN*PIT;    // NG*NN = 32KB staged h
    float* sc = sh + NG*NN;     // NN
    float* sp = sc + NN;        // NT
    int tid = threadIdx.x;
    int r = tid & (NN-1), q = tid >> 7;
    int b = blockIdx.x;
    const float* AdS = g_pow[1];   // Ad^32 after 5 squarings
    for (int idx = tid; idx < NN*NN; idx += NT) {
        int i = idx >> 7, j = idx & (NN-1);
        sA[i*PIT + j] = AdS[idx];
    }
    // stage all h for this batch: 2048 float4 loads
    {
        const float4* hg = (const float4*)(g_h + b*NG*NN);
        float4* sh4 = (float4*)sh;
        #pragma unroll
        for (int u = 0; u < 4; u++)
            sh4[tid + NT*u] = __ldg(hg + tid + NT*u);
    }
    if (tid < NN) sc[tid] = 0.0f;
    __syncthreads();
    float a[32];
    #pragma unroll
    for (int u = 0; u < 32; u++) a[u] = sA[r*PIT + 32*q + u];

    float cn = 0.0f;
    for (int g = 0; g < NG; g++) {
        if (q == 0) g_bound[(b*NG + g)*NN + r] = cn;   // fire-and-forget
        float acc0 = (q == 0) ? sh[g*NN + r] : 0.f;    // smem, not global
        float acc1 = 0.f, acc2 = 0.f, acc3 = 0.f;
        const float4* sc4 = (const float4*)sc;
        #pragma unroll
        for (int u4 = 0; u4 < 8; u4++) {
            float4 v = sc4[8*q + u4];
            acc0 = fmaf(a[4*u4+0], v.x, acc0);
            acc1 = fmaf(a[4*u4+1], v.y, acc1);
            acc2 = fmaf(a[4*u4+2], v.z, acc2);
            acc3 = fmaf(a[4*u4+3], v.w, acc3);
        }
        sp[q*NN + r] = (acc0 + acc1) + (acc2 + acc3);
        __syncthreads();
        if (q == 0) {
            cn = (sp[r] + sp[NN+r]) + (sp[2*NN+r] + sp[3*NN+r]);
            sc[r] = cn;
        }
        __syncthreads();
    }
}

// ============================================================
// Kernel 5: FUSED phase C + expand, TWO-PASS (measured 53.5us).
// ============================================================
__global__ __launch_bounds__(NT, 1) void k_fusedC(const float* __restrict__ f,
                                                  const float* __restrict__ Cv,
                                                  const float* __restrict__ Dv,
                                                  float* __restrict__ ys,
                                                  float* __restrict__ cfin) {
    extern __shared__ float sm[];
    float* sAd = sm;               // NN*PIT
    float* sSt = sAd + NN*PIT;     // CH*NN states
    float* sc  = sSt + CH*NN;      // NN current state
    float* sf  = sc + NN;          // CH
    float* sC  = sf + CH;          // NN
    float* sp  = sC + NN;          // NT
    int tid = threadIdx.x;
    int r = tid & (NN-1), q = tid >> 7;
    int g = blockIdx.x, b = blockIdx.y;

    for (int idx = tid; idx < NN*NN; idx += NT) {
        int i = idx >> 7, j = idx & (NN-1);
        sAd[i*PIT + j] = g_Ad[idx];
    }
    if (tid < CH) sf[tid] = f[b*LL + g*CH + tid];
    if (tid < NN) {
        sC[tid] = Cv[tid];
        sc[tid] = g_bound[(b*NG + g)*NN + tid];
    }
    __syncthreads();

    float a[32];
    #pragma unroll
    for (int u = 0; u < 32; u++) a[u] = sAd[r*PIT + 32*q + u];
    float bd  = (q == 0) ? g_Bd[r] : 0.0f;
    float dv0 = Dv[0];

    // ---- pass 1: recurrence into sSt ----
    for (int t = 0; t < CH; t++) {
        float acc0 = (q == 0) ? bd * sf[t] : 0.f;
        float acc1 = 0.f, acc2 = 0.f, acc3 = 0.f;
        const float4* sc4 = (const float4*)sc;
        #pragma unroll
        for (int u4 = 0; u4 < 8; u4++) {
            float4 v = sc4[8*q + u4];
            acc0 = fmaf(a[4*u4+0], v.x, acc0);
            acc1 = fmaf(a[4*u4+1], v.y, acc1);
            acc2 = fmaf(a[4*u4+2], v.z, acc2);
            acc3 = fmaf(a[4*u4+3], v.w, acc3);
        }
        sp[q*NN + r] = (acc0 + acc1) + (acc2 + acc3);
        __syncthreads();
        if (q == 0) {
            float cn = (sp[r] + sp[NN+r]) + (sp[2*NN+r] + sp[3*NN+r]);
            sc[r] = cn;
            sSt[t*NN + r] = cn;
        }
        __syncthreads();
    }

    // ---- pass 2: barrier-free streaming store ----
    float cn_[8];
    int nb = tid >> 5;
    #pragma unroll
    for (int it = 0; it < 8; it++) cn_[it] = sC[nb + 16*it];
    int lane = tid & 31;
    float4* outbase = (float4*)(ys + (size_t)(b*LL + g*CH) * NN * NN);
    const float4* st4 = (const float4*)sSt;

    for (int t = 0; t < CH; t++) {
        float4 cv = st4[t*(NN/4) + lane];
        float  df = dv0 * sf[t];
        float4* out = outbase + (size_t)t * (NN*NN/4);
        #pragma unroll
        for (int it = 0; it < 8; it++) {
            int idx = tid + NT*it;
            float4 v;
            v.x = fmaf(cn_[it], cv.x, df);
            v.y = fmaf(cn_[it], cv.y, df);
            v.z = fmaf(cn_[it], cv.z, df);
            v.w = fmaf(cn_[it], cv.w, df);
            __stcs(&out[idx], v);
        }
    }
    if (cfin != nullptr && g == NG-1 && tid < NN)
        cfin[b*NN + tid] = sSt[(CH-1)*NN + tid];
}

// ============================================================
extern "C" void kernel_launch(void* const* d_in, const int* in_sizes, int n_in,
                              void* d_out, int out_size) {
    const float* f = (const float*)d_in[0];
    const float* A = (const float*)d_in[1];
    const float* B = (const float*)d_in[2];
    const float* C = (const float*)d_in[3];
    const float* D = (const float*)d_in[4];
    float* out = (float*)d_out;

    const long long ysz = (long long)BATCH * LL * NN * NN;   // 67108864
    const int cf = BATCH * NN;                               // 256
    float* cfin = nullptr;
    float* ys   = out;
    if ((long long)out_size == ysz + cf) { cfin = out; ys = out + cf; }

    const int smem_disc = (2*NN*PIT + 4096)*4;               // 148480
    const int smem_sq5  = NN*NN*4;                           // 65536
    const int smem_pA   = (NN*PIT + NN + CH + NT)*4;         // 68736
    const int smem_pB   = (NN*PIT + NG*NN + NN + NT)*4;      // 101376
    const int smem_fC   = (NN*PIT + CH*NN + NN + CH + NN + NT)*4; // 85632
    cudaFuncSetAttribute(k_disc,   cudaFuncAttributeMaxDynamicSharedMemorySize, smem_disc);
    cudaFuncSetAttribute(k_sq5,    cudaFuncAttributeMaxDynamicSharedMemorySize, smem_sq5);
    cudaFuncSetAttribute(k_phaseA, cudaFuncAttributeMaxDynamicSharedMemorySize, smem_pA);
    cudaFuncSetAttribute(k_phaseB, cudaFuncAttributeMaxDynamicSharedMemorySize, smem_pB);
    cudaFuncSetAttribute(k_fusedC, cudaFuncAttributeMaxDynamicSharedMemorySize, smem_fC);

    // 1) discretize (D&C triangular inverse, one block)
    k_disc<<<1, 1024, smem_disc>>>(A);
    // 2) Bd + Ad^32 via 5 in-kernel squarings (cluster)
    k_sq5<<<8, 1024, smem_sq5>>>(B);
    // 3) phase A — local chunk contributions
    dim3 gA(NG, BATCH);
    k_phaseA<<<gA, NT, smem_pA>>>(f);
    // 4) boundary prefix (h pre-staged in smem)
    k_phaseB<<<BATCH, NT, smem_pB>>>();
    // 5) fused phase C + expand (two-pass streaming store)
    k_fusedC<<<gA, NT, smem_fC>>>(f, C, D, ys, cfin);
}